// round 7
// baseline (speedup 1.0000x reference)
#include <cuda_runtime.h>
#include <cuda_bf16.h>

#define HIDDEN   64
#define SEQ_LEN  128
#define BATCH    64
#define NPTS     (BATCH * SEQ_LEN)   // 8192
#define T_MAX_V  20.0f
#define KTERMS   40
#define NBLK_B   512

// ---------------- device scratch ----------------
// g_nl/g_done/g_ll: statically zeroed; the LAST reward block resets them after
// finalize, so every execution (correctness run + each graph replay) starts at 0.
__device__ float  g_lc[NPTS];
__device__ int    g_nl   = 0;
__device__ int    g_done = 0;
__device__ double g_ll   = 0.0;
__device__ double g_Me[KTERMS];   // overwritten (not accumulated) each run
__device__ double g_Ml[KTERMS];   // overwritten (not accumulated) each run

// c_k = 2^k / k!
__constant__ double c_coef[KTERMS] = {
    1.0, 2.0, 2.0, 1.3333333333333333, 0.6666666666666666,
    0.26666666666666666, 0.08888888888888889, 0.025396825396825397,
    0.006349206349206349, 0.0014109347442680775, 2.821869488536155e-04,
    5.130671797338464e-05, 8.551119662230773e-06, 1.3155568711124266e-06,
    1.8793669587320378e-07, 2.505822611642717e-08, 3.132278264553396e-09,
    3.6850332524157603e-10, 4.0944813915730673e-11, 4.3099804121822816e-12,
    4.3099804121822815e-13, 4.104743249697411e-14, 3.7315847724521917e-15,
    3.244856323871471e-16, 2.7040469365595593e-17, 2.1632375492476474e-18,
    1.6640288840366519e-19, 1.2326139881753718e-20, 8.804385629824085e-22,
    6.072024572292472e-23, 4.048016381528315e-24, 2.6116234719537516e-25,
    1.6322646699710948e-26, 9.892513151339969e-28, 5.819125383141158e-29,
    3.325214504652090e-30, 1.847341391473383e-31, 9.985629143099369e-33,
    5.255594285841772e-34, 2.695176556841934e-35
};

// ---------------- helpers ----------------
__device__ __forceinline__ unsigned long long pk2(float lo, float hi) {
    unsigned long long u;
    asm("mov.b64 %0, {%1, %2};" : "=l"(u) : "f"(lo), "f"(hi));
    return u;
}
__device__ __forceinline__ void upk2(unsigned long long u, float& lo, float& hi) {
    asm("mov.b64 {%0, %1}, %2;" : "=f"(lo), "=f"(hi) : "l"(u));
}
#define FFMA2(acc, a, b) \
    asm("fma.rn.f32x2 %0, %1, %2, %0;" : "+l"(acc) : "l"(a), "l"(b))

__device__ __forceinline__ float tanh_apx(float x) {
    float y;
    asm("tanh.approx.f32 %0, %1;" : "=f"(y) : "f"(x));
    return y;
}
__device__ __forceinline__ float sigm_apx(float x) {
    return fmaf(tanh_apx(0.5f * x), 0.5f, 0.5f);
}

#define BAR_SYNC(id, cnt)   asm volatile("bar.sync %0, %1;"   :: "r"(id), "r"(cnt) : "memory")
#define BAR_ARRIVE(id, cnt) asm volatile("bar.arrive %0, %1;" :: "r"(id), "r"(cnt) : "memory")

// ================= kernel 1: rollout (64 blocks x 288) =================
// W0: matvec rows 0-31 + LSTM update (2 units/lane)
// W1-7: matvec rows 32-255
// W8: sigma/cum chain (overlapped with matvec)
__global__ void __launch_bounds__(288, 1)
pp_rollout_kernel(const float* __restrict__ pool,
                  const float* __restrict__ Wih,
                  const float* __restrict__ Whh,
                  const float* __restrict__ bih,
                  const float* __restrict__ bhh,
                  const float* __restrict__ Vw,
                  const float* __restrict__ Vb) {
    const int b    = blockIdx.x;
    const int tid  = threadIdx.x;
    const int wid  = tid >> 5;
    const int lane = tid & 31;

    __shared__ __align__(16) float hx_s[HIDDEN];
    __shared__ __align__(16) float m_s[4 * HIDDEN];
    __shared__ __align__(16) float lg_s[SEQ_LEN];
    __shared__ __align__(16) float cum_hist[SEQ_LEN];
    __shared__ float red_s[64];     // [0..31] data, rest scratch pad
    __shared__ float cum_s;

    // matvec weight preload (rows 0..255)
    unsigned long long w2[32];
    float bias = 0.f;
    if (tid < 256) {
        const float4* wrow = (const float4*)(Whh + tid * HIDDEN);
#pragma unroll
        for (int q = 0; q < 16; q++) {
            float4 v = wrow[q];
            w2[2 * q]     = pk2(v.x, v.y);
            w2[2 * q + 1] = pk2(v.z, v.w);
        }
        bias = bih[tid] + bhh[tid];
    }
    const float vb = Vb[0];

    // update-warp preload (W0: units lane and lane+32)
    float wi1 = 0, wf1 = 0, wg1 = 0, wo1 = 0, vw1 = 0;
    float wi2 = 0, wf2 = 0, wg2 = 0, wo2 = 0, vw2 = 0;
    if (wid == 0) {
        wi1 = Wih[lane];            wi2 = Wih[lane + 32];
        wf1 = Wih[lane + 64];       wf2 = Wih[lane + 96];
        wg1 = Wih[lane + 128];      wg2 = Wih[lane + 160];
        wo1 = Wih[lane + 192];      wo2 = Wih[lane + 224];
        vw1 = Vw[lane];             vw2 = Vw[lane + 32];
    }
    if (tid < HIDDEN) hx_s[tid] = 0.f;
    if (tid < 64)     red_s[tid] = 0.f;
    if (tid < SEQ_LEN) lg_s[tid] = -__logf(pool[b * SEQ_LEN + tid]);

    float cx1 = 0.f, cx2 = 0.f;   // W0 cell states
    float cum_v = 0.f;            // W8 lane 0
    __syncthreads();

    for (int s = 0; s < SEQ_LEN; s++) {
        // ---------------- phase A ----------------
        if (wid < 8) {
            // matvec row tid: m = bias + Whh[tid,:] @ hx
            unsigned long long acc0 = pk2(bias, 0.f);
            unsigned long long acc1 = 0ull, acc2 = 0ull, acc3 = 0ull;
            const ulonglong2* h4 = (const ulonglong2*)hx_s;
#pragma unroll
            for (int j = 0; j < 8; j++) {
                ulonglong2 ha = h4[2 * j];
                ulonglong2 hb = h4[2 * j + 1];
                FFMA2(acc0, w2[4 * j + 0], ha.x);
                FFMA2(acc1, w2[4 * j + 1], ha.y);
                FFMA2(acc2, w2[4 * j + 2], hb.x);
                FFMA2(acc3, w2[4 * j + 3], hb.y);
            }
            float a0, a1, b0, b1, c0, c1, d0, d1;
            upk2(acc0, a0, a1); upk2(acc1, b0, b1);
            upk2(acc2, c0, c1); upk2(acc3, d0, d1);
            m_s[tid] = ((a0 + a1) + (b0 + b1)) + ((c0 + c1) + (d0 + d1));
        } else {
            // sigma/cum chain: fold 32 partials -> 8, then 3-level butterfly.
            // Lanes >= 8 read scratch (red_s[32..55]) and are discarded.
            float x = (red_s[lane] + red_s[lane + 8])
                    + (red_s[lane + 16] + red_s[lane + 24]);
            x += __shfl_xor_sync(0xffffffffu, x, 4);
            x += __shfl_xor_sync(0xffffffffu, x, 2);
            x += __shfl_xor_sync(0xffffffffu, x, 1);
            if (lane == 0) {
                float z = x + vb;
                float sigma = (z > 0.f ? z : (__expf(z) - 1.f)) + 1.f;   // elu + 1
                cum_v += __fdividef(lg_s[s], sigma);
                cum_s = cum_v;
                cum_hist[s] = cum_v;
            }
        }

        // ---------------- phase B ----------------
        if (wid == 0) {
            BAR_SYNC(1, 288);        // wait: all m_s + cum_s ready
            const float cum = cum_s;
            float mi1 = m_s[lane],       mi2 = m_s[lane + 32];
            float mf1 = m_s[lane + 64],  mf2 = m_s[lane + 96];
            float mg1 = m_s[lane + 128], mg2 = m_s[lane + 160];
            float mo1 = m_s[lane + 192], mo2 = m_s[lane + 224];

            float ig1 = sigm_apx(fmaf(cum, wi1, mi1));
            float fg1 = sigm_apx(fmaf(cum, wf1, mf1));
            float gt1 = tanh_apx(fmaf(cum, wg1, mg1));
            float og1 = sigm_apx(fmaf(cum, wo1, mo1));
            cx1 = fmaf(fg1, cx1, ig1 * gt1);
            float h1 = og1 * tanh_apx(cx1);

            float ig2 = sigm_apx(fmaf(cum, wi2, mi2));
            float fg2 = sigm_apx(fmaf(cum, wf2, mf2));
            float gt2 = tanh_apx(fmaf(cum, wg2, mg2));
            float og2 = sigm_apx(fmaf(cum, wo2, mo2));
            cx2 = fmaf(fg2, cx2, ig2 * gt2);
            float h2 = og2 * tanh_apx(cx2);

            hx_s[lane]      = h1;
            hx_s[lane + 32] = h2;
            red_s[lane] = fmaf(h1, vw1, h2 * vw2);
            __syncwarp();
            BAR_ARRIVE(2, 288);      // release matvec + sigma warps
        } else {
            BAR_ARRIVE(1, 288);
            BAR_SYNC(2, 288);        // wait: hx_s / red_s updated
        }
    }
    __syncthreads();

    // ---------------- epilogue: compaction of valid times only ----------------
    if (tid < SEQ_LEN) {
        float t = cum_hist[tid];
        bool valid = (t > 0.f) && (t < T_MAX_V);
        unsigned bal = __ballot_sync(0xffffffffu, valid);
        int base = 0;
        if (lane == 0) base = atomicAdd(&g_nl, __popc(bal));
        base = __shfl_sync(0xffffffffu, base, 0);
        if (valid) g_lc[base + __popc(bal & ((1u << lane) - 1u))] = t;
    }
}

// ================= kernel 2: reward =================
// All 512 blocks: symmetric ll pair sum.
// Blocks 0-39:  learner moment k (direct write, single owner).
// Blocks 40-79: expert moment k  (direct write, single owner).
// Last block:   finalize + reset globals for next replay.
__global__ void __launch_bounds__(128, 8)
pp_reward_kernel(const float* __restrict__ et, float* __restrict__ out) {
    const int T   = gridDim.x * blockDim.x;
    const int g   = blockIdx.x * blockDim.x + threadIdx.x;
    const int bk  = blockIdx.x;
    const int tid = threadIdx.x;
    const int wrp = tid >> 5, lane = tid & 31;
    const int nl  = g_nl;

    // ---- ll pair sum (j > i, symmetric) ----
    float acc = 0.f;
    if (nl > 0) {
        const int R = T / nl;
        if (g < R * nl) {
            const int i  = g % nl;
            const int r0 = g / nl;
            const float ti = g_lc[i];
            for (int j = i + 1 + r0; j < nl; j += R) {
                float d = ti - g_lc[j];
                acc += __expf(-d * d);
            }
        }
    }
    __shared__ float bsum[4];
#pragma unroll
    for (int o = 16; o > 0; o >>= 1) acc += __shfl_xor_sync(0xffffffffu, acc, o);
    if (lane == 0) bsum[wrp] = acc;
    __syncthreads();
    if (tid == 0) {
        double s = (double)bsum[0] + (double)bsum[1] + (double)bsum[2] + (double)bsum[3];
        atomicAdd(&g_ll, s);
    }

    // ---- moment blocks ----
    if (bk < 80) {
        const bool lrn = (bk < 40);
        const int  k   = lrn ? bk : bk - 40;
        const int  n   = lrn ? nl : NPTS;
        float macc = 0.f;
        for (int p = tid; p < n; p += 128) {
            float t = lrn ? g_lc[p] : et[p];
            // t<8: beyond it exp(-t^2) < e^-64 -> negligible; also avoids t^k overflow.
            bool ok = (t > 0.f) && (t < 8.f);
            float wp = ok ? __expf(-t * t) : 0.f;
            // t^k via square-and-multiply; tb=0 for invalid t so base never
            // overflows to Inf (0*Inf = NaN was the R6 bug).
            float base = ok ? t : 0.f;
            int kk = k;
            while (kk) { if (kk & 1) wp *= base; base *= base; kk >>= 1; }
            macc += wp;
        }
        __shared__ float msum[4];
#pragma unroll
        for (int o = 16; o > 0; o >>= 1) macc += __shfl_xor_sync(0xffffffffu, macc, o);
        if (lane == 0) msum[wrp] = macc;
        __syncthreads();
        if (tid == 0) {
            double s = (double)msum[0] + (double)msum[1] + (double)msum[2] + (double)msum[3];
            if (lrn) g_Ml[k] = s; else g_Me[k] = s;
        }
    }

    // ---- last-block finalize + reset ----
    __threadfence();
    __shared__ int is_last;
    if (tid == 0)
        is_last = (atomicAdd(&g_done, 1) == (int)gridDim.x - 1);
    __syncthreads();
    if (is_last) {
        __shared__ double t_ee[KTERMS], t_le[KTERMS];
        if (tid < KTERMS) {
            double c  = c_coef[tid];
            double me = g_Me[tid];
            t_ee[tid] = c * me * me;
            t_le[tid] = c * me * g_Ml[tid];
        }
        __syncthreads();
        if (tid == 0) {
            double e0 = 0, e1 = 0, e2 = 0, e3 = 0, l0 = 0, l1 = 0, l2 = 0, l3 = 0;
#pragma unroll
            for (int k = 0; k < KTERMS; k += 4) {
                e0 += t_ee[k]; e1 += t_ee[k + 1]; e2 += t_ee[k + 2]; e3 += t_ee[k + 3];
                l0 += t_le[k]; l1 += t_le[k + 1]; l2 += t_le[k + 2]; l3 += t_le[k + 3];
            }
            double ee = (e0 + e1) + (e2 + e3);
            double le = (l0 + l1) + (l2 + l3);
            double ll = 2.0 * g_ll + (double)nl;   // off-diag*2 + diagonal
            out[0] = (float)(ee + ll - 2.0 * le);
            // reset for next replay (graph-safe: every run ends zeroed)
            g_nl = 0; g_done = 0; g_ll = 0.0;
        }
    }
}

// ---------------- launch ----------------
extern "C" void kernel_launch(void* const* d_in, const int* in_sizes, int n_in,
                              void* d_out, int out_size) {
    const float* pool = (const float*)d_in[0];
    const float* et   = (const float*)d_in[1];
    const float* Wih  = (const float*)d_in[2];
    const float* Whh  = (const float*)d_in[3];
    const float* bih  = (const float*)d_in[4];
    const float* bhh  = (const float*)d_in[5];
    const float* Vw   = (const float*)d_in[6];
    const float* Vb   = (const float*)d_in[7];
    float* out = (float*)d_out;

    pp_rollout_kernel<<<BATCH, 288>>>(pool, Wih, Whh, bih, bhh, Vw, Vb);
    pp_reward_kernel<<<NBLK_B, 128>>>(et, out);
}

// round 8
// speedup vs baseline: 1.1138x; 1.1138x over previous
#include <cuda_runtime.h>
#include <cuda_bf16.h>

#define HIDDEN   64
#define SEQ_LEN  128
#define BATCH    64
#define NPTS     (BATCH * SEQ_LEN)   // 8192
#define T_MAX_V  20.0f
#define KTERMS   40
#define NBLK_B   256                 // reward grid
#define NTHR_B   256

// ---------------- device scratch ----------------
// g_nl starts 0 and is reset by the finalize kernel each run (graph-safe).
// Everything else is overwritten (not accumulated) every run.
__device__ float  g_lc[NPTS];
__device__ int    g_nl = 0;
__device__ float  g_llp[NBLK_B];
__device__ double g_Me[KTERMS];
__device__ double g_Ml[KTERMS];

// c_k = 2^k / k!
__constant__ double c_coef[KTERMS] = {
    1.0, 2.0, 2.0, 1.3333333333333333, 0.6666666666666666,
    0.26666666666666666, 0.08888888888888889, 0.025396825396825397,
    0.006349206349206349, 0.0014109347442680775, 2.821869488536155e-04,
    5.130671797338464e-05, 8.551119662230773e-06, 1.3155568711124266e-06,
    1.8793669587320378e-07, 2.505822611642717e-08, 3.132278264553396e-09,
    3.6850332524157603e-10, 4.0944813915730673e-11, 4.3099804121822816e-12,
    4.3099804121822815e-13, 4.104743249697411e-14, 3.7315847724521917e-15,
    3.244856323871471e-16, 2.7040469365595593e-17, 2.1632375492476474e-18,
    1.6640288840366519e-19, 1.2326139881753718e-20, 8.804385629824085e-22,
    6.072024572292472e-23, 4.048016381528315e-24, 2.6116234719537516e-25,
    1.6322646699710948e-26, 9.892513151339969e-28, 5.819125383141158e-29,
    3.325214504652090e-30, 1.847341391473383e-31, 9.985629143099369e-33,
    5.255594285841772e-34, 2.695176556841934e-35
};

// ---------------- helpers ----------------
__device__ __forceinline__ unsigned long long pk2(float lo, float hi) {
    unsigned long long u;
    asm("mov.b64 %0, {%1, %2};" : "=l"(u) : "f"(lo), "f"(hi));
    return u;
}
__device__ __forceinline__ void upk2(unsigned long long u, float& lo, float& hi) {
    asm("mov.b64 {%0, %1}, %2;" : "=f"(lo), "=f"(hi) : "l"(u));
}
#define FFMA2(acc, a, b) \
    asm("fma.rn.f32x2 %0, %1, %2, %0;" : "+l"(acc) : "l"(a), "l"(b))
#define FADD2(dst, a, b) \
    asm("add.rn.f32x2 %0, %1, %2;" : "=l"(dst) : "l"(a), "l"(b))

__device__ __forceinline__ float tanh_apx(float x) {
    float y;
    asm("tanh.approx.f32 %0, %1;" : "=f"(y) : "f"(x));
    return y;
}
__device__ __forceinline__ float sigm_apx(float x) {
    return fmaf(tanh_apx(0.5f * x), 0.5f, 0.5f);
}

#define BAR_SYNC(id, cnt)   asm volatile("bar.sync %0, %1;"   :: "r"(id), "r"(cnt) : "memory")
#define BAR_ARRIVE(id, cnt) asm volatile("bar.arrive %0, %1;" :: "r"(id), "r"(cnt) : "memory")

// ================= kernel 1: rollout (64 blocks x 288) =================
// W0: matvec rows 0-31 + LSTM update (2 units/lane)
// W1-7: matvec rows 32-255
// W8: sigma/cum chain (overlapped with matvec)
__global__ void __launch_bounds__(288, 1)
pp_rollout_kernel(const float* __restrict__ pool,
                  const float* __restrict__ Wih,
                  const float* __restrict__ Whh,
                  const float* __restrict__ bih,
                  const float* __restrict__ bhh,
                  const float* __restrict__ Vw,
                  const float* __restrict__ Vb) {
    const int b    = blockIdx.x;
    const int tid  = threadIdx.x;
    const int wid  = tid >> 5;
    const int lane = tid & 31;

    __shared__ __align__(16) float hx_s[HIDDEN];
    __shared__ __align__(16) float m_s[4 * HIDDEN];
    __shared__ __align__(16) float lg_s[SEQ_LEN];
    __shared__ __align__(16) float cum_hist[SEQ_LEN];
    __shared__ float red_s[64];     // [0..31] data, rest scratch pad
    __shared__ float cum_s;

    // matvec weight preload (rows 0..255)
    unsigned long long w2[32];
    float bias = 0.f;
    if (tid < 256) {
        const float4* wrow = (const float4*)(Whh + tid * HIDDEN);
#pragma unroll
        for (int q = 0; q < 16; q++) {
            float4 v = wrow[q];
            w2[2 * q]     = pk2(v.x, v.y);
            w2[2 * q + 1] = pk2(v.z, v.w);
        }
        bias = bih[tid] + bhh[tid];
    }
    const float vb = Vb[0];

    // update-warp preload (W0: units lane and lane+32)
    float wi1 = 0, wf1 = 0, wg1 = 0, wo1 = 0, vw1 = 0;
    float wi2 = 0, wf2 = 0, wg2 = 0, wo2 = 0, vw2 = 0;
    if (wid == 0) {
        wi1 = Wih[lane];            wi2 = Wih[lane + 32];
        wf1 = Wih[lane + 64];       wf2 = Wih[lane + 96];
        wg1 = Wih[lane + 128];      wg2 = Wih[lane + 160];
        wo1 = Wih[lane + 192];      wo2 = Wih[lane + 224];
        vw1 = Vw[lane];             vw2 = Vw[lane + 32];
    }
    if (tid < HIDDEN) hx_s[tid] = 0.f;
    if (tid < 64)     red_s[tid] = 0.f;
    if (tid < SEQ_LEN) lg_s[tid] = -__logf(pool[b * SEQ_LEN + tid]);

    float cx1 = 0.f, cx2 = 0.f;   // W0 cell states
    float cum_v = 0.f;            // W8 lane 0
    __syncthreads();

    for (int s = 0; s < SEQ_LEN; s++) {
        // ---------------- phase A ----------------
        if (wid < 8) {
            // matvec row tid: m = bias + Whh[tid,:] @ hx
            unsigned long long acc0 = pk2(bias, 0.f);
            unsigned long long acc1 = 0ull, acc2 = 0ull, acc3 = 0ull;
            const ulonglong2* h4 = (const ulonglong2*)hx_s;
#pragma unroll
            for (int j = 0; j < 8; j++) {
                ulonglong2 ha = h4[2 * j];
                ulonglong2 hb = h4[2 * j + 1];
                FFMA2(acc0, w2[4 * j + 0], ha.x);
                FFMA2(acc1, w2[4 * j + 1], ha.y);
                FFMA2(acc2, w2[4 * j + 2], hb.x);
                FFMA2(acc3, w2[4 * j + 3], hb.y);
            }
            unsigned long long p0, p1, pz;
            FADD2(p0, acc0, acc1);
            FADD2(p1, acc2, acc3);
            FADD2(pz, p0, p1);
            float lo, hi;
            upk2(pz, lo, hi);
            m_s[tid] = lo + hi;
        } else {
            // sigma/cum chain: fold 32 partials -> 8, then 3-level butterfly.
            // Lanes >= 8 read scratch (red_s[32..55]) and are discarded.
            float x = (red_s[lane] + red_s[lane + 8])
                    + (red_s[lane + 16] + red_s[lane + 24]);
            x += __shfl_xor_sync(0xffffffffu, x, 4);
            x += __shfl_xor_sync(0xffffffffu, x, 2);
            x += __shfl_xor_sync(0xffffffffu, x, 1);
            if (lane == 0) {
                float z = x + vb;
                float sigma = (z > 0.f ? z : (__expf(z) - 1.f)) + 1.f;   // elu + 1
                cum_v += __fdividef(lg_s[s], sigma);
                cum_s = cum_v;
                cum_hist[s] = cum_v;
            }
        }

        // ---------------- phase B ----------------
        if (wid == 0) {
            BAR_SYNC(1, 288);        // wait: all m_s + cum_s ready
            const float cum = cum_s;
            float mi1 = m_s[lane],       mi2 = m_s[lane + 32];
            float mf1 = m_s[lane + 64],  mf2 = m_s[lane + 96];
            float mg1 = m_s[lane + 128], mg2 = m_s[lane + 160];
            float mo1 = m_s[lane + 192], mo2 = m_s[lane + 224];

            float ig1 = sigm_apx(fmaf(cum, wi1, mi1));
            float fg1 = sigm_apx(fmaf(cum, wf1, mf1));
            float gt1 = tanh_apx(fmaf(cum, wg1, mg1));
            float og1 = sigm_apx(fmaf(cum, wo1, mo1));
            cx1 = fmaf(fg1, cx1, ig1 * gt1);
            float h1 = og1 * tanh_apx(cx1);

            float ig2 = sigm_apx(fmaf(cum, wi2, mi2));
            float fg2 = sigm_apx(fmaf(cum, wf2, mf2));
            float gt2 = tanh_apx(fmaf(cum, wg2, mg2));
            float og2 = sigm_apx(fmaf(cum, wo2, mo2));
            cx2 = fmaf(fg2, cx2, ig2 * gt2);
            float h2 = og2 * tanh_apx(cx2);

            hx_s[lane]      = h1;
            hx_s[lane + 32] = h2;
            red_s[lane] = fmaf(h1, vw1, h2 * vw2);
            __syncwarp();
            BAR_ARRIVE(2, 288);      // release matvec + sigma warps
        } else {
            BAR_ARRIVE(1, 288);
            BAR_SYNC(2, 288);        // wait: hx_s / red_s updated
        }
    }
    __syncthreads();

    // ---------------- epilogue: compaction of valid times only ----------------
    if (tid < SEQ_LEN) {
        float t = cum_hist[tid];
        bool valid = (t > 0.f) && (t < T_MAX_V);
        unsigned bal = __ballot_sync(0xffffffffu, valid);
        int base = 0;
        if (lane == 0) base = atomicAdd(&g_nl, __popc(bal));
        base = __shfl_sync(0xffffffffu, base, 0);
        if (valid) g_lc[base + __popc(bal & ((1u << lane) - 1u))] = t;
    }
}

// ================= kernel 2: reward (256 blocks x 256) =================
// All blocks: symmetric ll pair partial -> g_llp[bk] (distinct slots, no atomics).
// Blocks 0-39:  learner moment k (single-owner write).
// Blocks 40-79: expert moment k  (single-owner write).
__global__ void __launch_bounds__(NTHR_B, 4)
pp_reward_kernel(const float* __restrict__ et) {
    const int T   = NBLK_B * NTHR_B;
    const int g   = blockIdx.x * NTHR_B + threadIdx.x;
    const int bk  = blockIdx.x;
    const int tid = threadIdx.x;
    const int wrp = tid >> 5, lane = tid & 31;
    const int nl  = g_nl;

    // ---- ll pair sum (j > i, symmetric) ----
    float acc = 0.f;
    if (nl > 0) {
        const int R = T / nl;
        if (g < R * nl) {
            const int i  = g % nl;
            const int r0 = g / nl;
            const float ti = g_lc[i];
            for (int j = i + 1 + r0; j < nl; j += R) {
                float d = ti - g_lc[j];
                acc += __expf(-d * d);
            }
        }
    }
    __shared__ float bsum[8];
#pragma unroll
    for (int o = 16; o > 0; o >>= 1) acc += __shfl_xor_sync(0xffffffffu, acc, o);
    if (lane == 0) bsum[wrp] = acc;
    __syncthreads();
    if (tid == 0) {
        float s = ((bsum[0] + bsum[1]) + (bsum[2] + bsum[3]))
                + ((bsum[4] + bsum[5]) + (bsum[6] + bsum[7]));
        g_llp[bk] = s;
    }

    // ---- moment blocks ----
    if (bk < 80) {
        const bool lrn = (bk < 40);
        const int  k   = lrn ? bk : bk - 40;
        const int  n   = lrn ? nl : NPTS;
        float macc = 0.f;
        for (int p = tid; p < n; p += NTHR_B) {
            float t = lrn ? g_lc[p] : et[p];
            // t<8: beyond it exp(-t^2) < e^-64 -> negligible; also avoids t^k overflow.
            bool ok = (t > 0.f) && (t < 8.f);
            float wp = ok ? __expf(-t * t) : 0.f;
            // t^k square-and-multiply; base forced to 0 when invalid so no Inf.
            float base = ok ? t : 0.f;
            int kk = k;
            while (kk) { if (kk & 1) wp *= base; base *= base; kk >>= 1; }
            macc += wp;
        }
        __shared__ float msum[8];
#pragma unroll
        for (int o = 16; o > 0; o >>= 1) macc += __shfl_xor_sync(0xffffffffu, macc, o);
        if (lane == 0) msum[wrp] = macc;
        __syncthreads();
        if (tid == 0) {
            double s = (double)((msum[0] + msum[1]) + (msum[2] + msum[3]))
                     + (double)((msum[4] + msum[5]) + (msum[6] + msum[7]));
            if (lrn) g_Ml[k] = s; else g_Me[k] = s;
        }
    }
}

// ================= kernel 3: finalize (1 block x 256) =================
__global__ void __launch_bounds__(NTHR_B, 1)
pp_finalize_kernel(float* __restrict__ out) {
    const int tid = threadIdx.x;
    const int wrp = tid >> 5, lane = tid & 31;

    // parallel sum of ll partials (256 slots, one per thread)
    double d = (double)g_llp[tid];
#pragma unroll
    for (int o = 16; o > 0; o >>= 1) d += __shfl_xor_sync(0xffffffffu, d, o);
    __shared__ double wsum[8];
    if (lane == 0) wsum[wrp] = d;

    // moment combination in parallel
    __shared__ double t_ee[KTERMS], t_le[KTERMS];
    if (tid < KTERMS) {
        double c  = c_coef[tid];
        double me = g_Me[tid];
        t_ee[tid] = c * me * me;
        t_le[tid] = c * me * g_Ml[tid];
    }
    __syncthreads();

    if (tid == 0) {
        double llp = ((wsum[0] + wsum[1]) + (wsum[2] + wsum[3]))
                   + ((wsum[4] + wsum[5]) + (wsum[6] + wsum[7]));
        double e0 = 0, e1 = 0, e2 = 0, e3 = 0, l0 = 0, l1 = 0, l2 = 0, l3 = 0;
#pragma unroll
        for (int k = 0; k < KTERMS; k += 4) {
            e0 += t_ee[k]; e1 += t_ee[k + 1]; e2 += t_ee[k + 2]; e3 += t_ee[k + 3];
            l0 += t_le[k]; l1 += t_le[k + 1]; l2 += t_le[k + 2]; l3 += t_le[k + 3];
        }
        double ee = (e0 + e1) + (e2 + e3);
        double le = (l0 + l1) + (l2 + l3);
        double ll = 2.0 * llp + (double)g_nl;   // off-diag*2 + diagonal
        out[0] = (float)(ee + ll - 2.0 * le);
        g_nl = 0;                                // reset for next replay
    }
}

// ---------------- launch ----------------
extern "C" void kernel_launch(void* const* d_in, const int* in_sizes, int n_in,
                              void* d_out, int out_size) {
    const float* pool = (const float*)d_in[0];
    const float* et   = (const float*)d_in[1];
    const float* Wih  = (const float*)d_in[2];
    const float* Whh  = (const float*)d_in[3];
    const float* bih  = (const float*)d_in[4];
    const float* bhh  = (const float*)d_in[5];
    const float* Vw   = (const float*)d_in[6];
    const float* Vb   = (const float*)d_in[7];
    float* out = (float*)d_out;

    pp_rollout_kernel<<<BATCH, 288>>>(pool, Wih, Whh, bih, bhh, Vw, Vb);
    pp_reward_kernel<<<NBLK_B, NTHR_B>>>(et);
    pp_finalize_kernel<<<1, NTHR_B>>>(out);
}

// round 9
// speedup vs baseline: 1.1459x; 1.0288x over previous
#include <cuda_runtime.h>
#include <cuda_bf16.h>

#define HIDDEN   64
#define SEQ_LEN  128
#define BATCH    64
#define NPTS     (BATCH * SEQ_LEN)   // 8192
#define T_MAX_V  20.0f
#define KTERMS   40
#define NBLK_B   256                 // reward grid
#define NTHR_B   256

// ---------------- device scratch ----------------
__device__ float  g_lc[NPTS];
__device__ int    g_nl = 0;          // reset by finalize each run (graph-safe)
__device__ float  g_llp[NBLK_B];
__device__ double g_Me[KTERMS];
__device__ double g_Ml[KTERMS];

// c_k = 2^k / k!
__constant__ double c_coef[KTERMS] = {
    1.0, 2.0, 2.0, 1.3333333333333333, 0.6666666666666666,
    0.26666666666666666, 0.08888888888888889, 0.025396825396825397,
    0.006349206349206349, 0.0014109347442680775, 2.821869488536155e-04,
    5.130671797338464e-05, 8.551119662230773e-06, 1.3155568711124266e-06,
    1.8793669587320378e-07, 2.505822611642717e-08, 3.132278264553396e-09,
    3.6850332524157603e-10, 4.0944813915730673e-11, 4.3099804121822816e-12,
    4.3099804121822815e-13, 4.104743249697411e-14, 3.7315847724521917e-15,
    3.244856323871471e-16, 2.7040469365595593e-17, 2.1632375492476474e-18,
    1.6640288840366519e-19, 1.2326139881753718e-20, 8.804385629824085e-22,
    6.072024572292472e-23, 4.048016381528315e-24, 2.6116234719537516e-25,
    1.6322646699710948e-26, 9.892513151339969e-28, 5.819125383141158e-29,
    3.325214504652090e-30, 1.847341391473383e-31, 9.985629143099369e-33,
    5.255594285841772e-34, 2.695176556841934e-35
};

// ---------------- helpers ----------------
__device__ __forceinline__ unsigned long long pk2(float lo, float hi) {
    unsigned long long u;
    asm("mov.b64 %0, {%1, %2};" : "=l"(u) : "f"(lo), "f"(hi));
    return u;
}
__device__ __forceinline__ void upk2(unsigned long long u, float& lo, float& hi) {
    asm("mov.b64 {%0, %1}, %2;" : "=f"(lo), "=f"(hi) : "l"(u));
}
#define FFMA2(acc, a, b) \
    asm("fma.rn.f32x2 %0, %1, %2, %0;" : "+l"(acc) : "l"(a), "l"(b))
#define FADD2(dst, a, b) \
    asm("add.rn.f32x2 %0, %1, %2;" : "=l"(dst) : "l"(a), "l"(b))

__device__ __forceinline__ float tanh_apx(float x) {
    float y;
    asm("tanh.approx.f32 %0, %1;" : "=f"(y) : "f"(x));
    return y;
}

// ================= kernel 1: rollout (64 blocks x 256) =================
// Warp w, lane l owns matvec row  gate*64 + w*8 + u   (gate = l>>3, u = l&7).
// Each warp therefore produces all 4 gates for ITS 8 hidden units:
// activations are exchanged by 3 intra-warp shuffles; lanes 0..7 update
// cx/h for the warp's units. The sigma/cum chain is computed redundantly
// by every warp (concurrent with the matvec). One __syncthreads per step;
// hx/red are double-buffered on step parity.
__global__ void __launch_bounds__(256, 1)
pp_rollout_kernel(const float* __restrict__ pool,
                  const float* __restrict__ Wih,
                  const float* __restrict__ Whh,
                  const float* __restrict__ bih,
                  const float* __restrict__ bhh,
                  const float* __restrict__ Vw,
                  const float* __restrict__ Vb) {
    const int b    = blockIdx.x;
    const int tid  = threadIdx.x;
    const int w    = tid >> 5;
    const int l    = tid & 31;
    const int gate = l >> 3;          // 0=i 1=f 2=g 3=o
    const int ug   = l & 7;           // unit within warp's group
    const int row  = gate * 64 + w * 8 + ug;

    __shared__ __align__(16) float hx_sb[2][HIDDEN];
    __shared__ __align__(16) float red_sb[2][8];
    __shared__ __align__(16) float lg_s[SEQ_LEN];
    __shared__ __align__(16) float cum_hist[SEQ_LEN];

    // preload W_hh row as packed f32x2
    unsigned long long w2[32];
    {
        const float4* wrow = (const float4*)(Whh + row * HIDDEN);
#pragma unroll
        for (int q = 0; q < 16; q++) {
            float4 v = wrow[q];
            w2[2 * q]     = pk2(v.x, v.y);
            w2[2 * q + 1] = pk2(v.z, v.w);
        }
    }
    const float wih  = Wih[row];
    const float bias = bih[row] + bhh[row];
    const float vb   = Vb[0];
    const bool  isg  = (gate == 2);
    const float vw   = (l < 8) ? Vw[w * 8 + l] : 0.f;

    if (tid < HIDDEN) hx_sb[0][tid] = 0.f;
    if (tid < 8)      red_sb[0][tid] = 0.f;
    if (tid < SEQ_LEN) lg_s[tid] = -__logf(pool[b * SEQ_LEN + tid]);

    float cx = 0.f;       // lanes 0..7: cell state of unit w*8+l
    float cum_v = 0.f;    // redundant in every lane of every warp
    __syncthreads();

    for (int s = 0; s < SEQ_LEN; s++) {
        const int p = s & 1;

        // ---- cum/sigma chain (redundant per warp; independent of matvec) ----
        const float4* r4 = (const float4*)red_sb[p];
        float4 ra = r4[0], rb = r4[1];
        float S = ((ra.x + ra.y) + (ra.z + ra.w)) + ((rb.x + rb.y) + (rb.z + rb.w));
        float z = S + vb;
        float sigma = (z > 0.f ? z : (__expf(z) - 1.f)) + 1.f;   // elu + 1
        cum_v += __fdividef(lg_s[s], sigma);

        // ---- matvec row: m = bias + Whh[row,:] @ hx ----
        unsigned long long acc0 = pk2(bias, 0.f);
        unsigned long long acc1 = 0ull, acc2 = 0ull, acc3 = 0ull;
        const ulonglong2* h4 = (const ulonglong2*)hx_sb[p];
#pragma unroll
        for (int j = 0; j < 8; j++) {
            ulonglong2 ha = h4[2 * j];
            ulonglong2 hb = h4[2 * j + 1];
            FFMA2(acc0, w2[4 * j + 0], ha.x);
            FFMA2(acc1, w2[4 * j + 1], ha.y);
            FFMA2(acc2, w2[4 * j + 2], hb.x);
            FFMA2(acc3, w2[4 * j + 3], hb.y);
        }
        unsigned long long p0, p1, pz;
        FADD2(p0, acc0, acc1);
        FADD2(p1, acc2, acc3);
        FADD2(pz, p0, p1);
        float lo, hi;
        upk2(pz, lo, hi);
        float gv = fmaf(cum_v, wih, lo + hi);

        // ---- activation (uniform: sigmoid via tanh identity) ----
        float pre = isg ? gv : 0.5f * gv;
        float tv  = tanh_apx(pre);
        float act = isg ? tv : fmaf(tv, 0.5f, 0.5f);

        // ---- gather gates to unit lanes (3 shuffles) ----
        float fv = __shfl_sync(0xffffffffu, act, ug + 8);
        float gg = __shfl_sync(0xffffffffu, act, ug + 16);
        float ov = __shfl_sync(0xffffffffu, act, ug + 24);
        // lane u<8 owns gate 0 (i) for its unit: iv = own act

        float hv = 0.f;
        if (l < 8) {
            cx = fmaf(fv, cx, act * gg);
            float h = ov * tanh_apx(cx);
            hx_sb[p ^ 1][w * 8 + l] = h;
            hv = h * vw;
        }
        // reduce hv over lanes 0..7 (tree stays within 0..7)
        hv += __shfl_xor_sync(0xffffffffu, hv, 1);
        hv += __shfl_xor_sync(0xffffffffu, hv, 2);
        hv += __shfl_xor_sync(0xffffffffu, hv, 4);
        if (l == 0) red_sb[p ^ 1][w] = hv;
        if (tid == 0) cum_hist[s] = cum_v;
        __syncthreads();
    }

    // ---------------- epilogue: compaction of valid times ----------------
    if (tid < SEQ_LEN) {
        float t = cum_hist[tid];
        bool valid = (t > 0.f) && (t < T_MAX_V);
        unsigned bal = __ballot_sync(0xffffffffu, valid);
        int base = 0;
        if (l == 0) base = atomicAdd(&g_nl, __popc(bal));
        base = __shfl_sync(0xffffffffu, base, 0);
        if (valid) g_lc[base + __popc(bal & ((1u << l) - 1u))] = t;
    }
}

// ================= kernel 2: reward (256 blocks x 256) =================
// All blocks: symmetric ll pair partial -> g_llp[bk] (distinct slots, no atomics).
// Blocks 0-39: learner moment k. Blocks 40-79: expert moment k.
__global__ void __launch_bounds__(NTHR_B, 4)
pp_reward_kernel(const float* __restrict__ et) {
    const int T   = NBLK_B * NTHR_B;
    const int g   = blockIdx.x * NTHR_B + threadIdx.x;
    const int bk  = blockIdx.x;
    const int tid = threadIdx.x;
    const int wrp = tid >> 5, lane = tid & 31;
    const int nl  = g_nl;

    // ---- ll pair sum (j > i, symmetric) ----
    float acc = 0.f;
    if (nl > 0) {
        const int R = T / nl;
        if (g < R * nl) {
            const int i  = g % nl;
            const int r0 = g / nl;
            const float ti = g_lc[i];
            for (int j = i + 1 + r0; j < nl; j += R) {
                float d = ti - g_lc[j];
                acc += __expf(-d * d);
            }
        }
    }
    __shared__ float bsum[8];
#pragma unroll
    for (int o = 16; o > 0; o >>= 1) acc += __shfl_xor_sync(0xffffffffu, acc, o);
    if (lane == 0) bsum[wrp] = acc;
    __syncthreads();
    if (tid == 0) {
        float s = ((bsum[0] + bsum[1]) + (bsum[2] + bsum[3]))
                + ((bsum[4] + bsum[5]) + (bsum[6] + bsum[7]));
        g_llp[bk] = s;
    }

    // ---- moment blocks ----
    if (bk < 80) {
        const bool lrn = (bk < 40);
        const int  k   = lrn ? bk : bk - 40;
        const int  n   = lrn ? nl : NPTS;
        float macc = 0.f;
        for (int p = tid; p < n; p += NTHR_B) {
            float t = lrn ? g_lc[p] : et[p];
            bool ok = (t > 0.f) && (t < 8.f);     // beyond 8: exp(-t^2) < e^-64
            float wp = ok ? __expf(-t * t) : 0.f;
            float base = ok ? t : 0.f;            // keep base finite -> no 0*Inf
            int kk = k;
            while (kk) { if (kk & 1) wp *= base; base *= base; kk >>= 1; }
            macc += wp;
        }
        __shared__ float msum[8];
#pragma unroll
        for (int o = 16; o > 0; o >>= 1) macc += __shfl_xor_sync(0xffffffffu, macc, o);
        if (lane == 0) msum[wrp] = macc;
        __syncthreads();
        if (tid == 0) {
            double s = (double)((msum[0] + msum[1]) + (msum[2] + msum[3]))
                     + (double)((msum[4] + msum[5]) + (msum[6] + msum[7]));
            if (lrn) g_Ml[k] = s; else g_Me[k] = s;
        }
    }
}

// ================= kernel 3: finalize (1 block x 256) =================
__global__ void __launch_bounds__(NTHR_B, 1)
pp_finalize_kernel(float* __restrict__ out) {
    const int tid = threadIdx.x;
    const int wrp = tid >> 5, lane = tid & 31;

    double d = (double)g_llp[tid];
#pragma unroll
    for (int o = 16; o > 0; o >>= 1) d += __shfl_xor_sync(0xffffffffu, d, o);
    __shared__ double wsum[8];
    if (lane == 0) wsum[wrp] = d;

    __shared__ double t_ee[KTERMS], t_le[KTERMS];
    if (tid < KTERMS) {
        double c  = c_coef[tid];
        double me = g_Me[tid];
        t_ee[tid] = c * me * me;
        t_le[tid] = c * me * g_Ml[tid];
    }
    __syncthreads();

    if (tid == 0) {
        double llp = ((wsum[0] + wsum[1]) + (wsum[2] + wsum[3]))
                   + ((wsum[4] + wsum[5]) + (wsum[6] + wsum[7]));
        double e0 = 0, e1 = 0, e2 = 0, e3 = 0, l0 = 0, l1 = 0, l2 = 0, l3 = 0;
#pragma unroll
        for (int k = 0; k < KTERMS; k += 4) {
            e0 += t_ee[k]; e1 += t_ee[k + 1]; e2 += t_ee[k + 2]; e3 += t_ee[k + 3];
            l0 += t_le[k]; l1 += t_le[k + 1]; l2 += t_le[k + 2]; l3 += t_le[k + 3];
        }
        double ee = (e0 + e1) + (e2 + e3);
        double le = (l0 + l1) + (l2 + l3);
        double ll = 2.0 * llp + (double)g_nl;   // off-diag*2 + diagonal
        out[0] = (float)(ee + ll - 2.0 * le);
        g_nl = 0;                                // reset for next replay
    }
}

// ---------------- launch ----------------
extern "C" void kernel_launch(void* const* d_in, const int* in_sizes, int n_in,
                              void* d_out, int out_size) {
    const float* pool = (const float*)d_in[0];
    const float* et   = (const float*)d_in[1];
    const float* Wih  = (const float*)d_in[2];
    const float* Whh  = (const float*)d_in[3];
    const float* bih  = (const float*)d_in[4];
    const float* bhh  = (const float*)d_in[5];
    const float* Vw   = (const float*)d_in[6];
    const float* Vb   = (const float*)d_in[7];
    float* out = (float*)d_out;

    pp_rollout_kernel<<<BATCH, 256>>>(pool, Wih, Whh, bih, bhh, Vw, Vb);
    pp_reward_kernel<<<NBLK_B, NTHR_B>>>(et);
    pp_finalize_kernel<<<1, NTHR_B>>>(out);
}

// round 10
// speedup vs baseline: 1.3600x; 1.1868x over previous
#include <cuda_runtime.h>
#include <cuda_bf16.h>

#define HIDDEN   64
#define SEQ_LEN  128
#define BATCH    64
#define NPTS     (BATCH * SEQ_LEN)   // 8192
#define T_MAX_V  20.0f
#define KTERMS   40
#define NBLK_B   256                 // reward grid
#define NTHR_B   256

// ---------------- device scratch ----------------
__device__ float  g_lc[NPTS];
__device__ int    g_nl = 0;          // reset by finalize each run (graph-safe)
__device__ float  g_llp[NBLK_B];
__device__ double g_Me[KTERMS];
__device__ double g_Ml[KTERMS];

// c_k = 2^k / k!
__constant__ double c_coef[KTERMS] = {
    1.0, 2.0, 2.0, 1.3333333333333333, 0.6666666666666666,
    0.26666666666666666, 0.08888888888888889, 0.025396825396825397,
    0.006349206349206349, 0.0014109347442680775, 2.821869488536155e-04,
    5.130671797338464e-05, 8.551119662230773e-06, 1.3155568711124266e-06,
    1.8793669587320378e-07, 2.505822611642717e-08, 3.132278264553396e-09,
    3.6850332524157603e-10, 4.0944813915730673e-11, 4.3099804121822816e-12,
    4.3099804121822815e-13, 4.104743249697411e-14, 3.7315847724521917e-15,
    3.244856323871471e-16, 2.7040469365595593e-17, 2.1632375492476474e-18,
    1.6640288840366519e-19, 1.2326139881753718e-20, 8.804385629824085e-22,
    6.072024572292472e-23, 4.048016381528315e-24, 2.6116234719537516e-25,
    1.6322646699710948e-26, 9.892513151339969e-28, 5.819125383141158e-29,
    3.325214504652090e-30, 1.847341391473383e-31, 9.985629143099369e-33,
    5.255594285841772e-34, 2.695176556841934e-35
};

// ---------------- helpers ----------------
__device__ __forceinline__ unsigned long long pk2(float lo, float hi) {
    unsigned long long u;
    asm("mov.b64 %0, {%1, %2};" : "=l"(u) : "f"(lo), "f"(hi));
    return u;
}
__device__ __forceinline__ void upk2(unsigned long long u, float& lo, float& hi) {
    asm("mov.b64 {%0, %1}, %2;" : "=f"(lo), "=f"(hi) : "l"(u));
}
#define FFMA2(acc, a, b) \
    asm("fma.rn.f32x2 %0, %1, %2, %0;" : "+l"(acc) : "l"(a), "l"(b))
#define FADD2(dst, a, b) \
    asm("add.rn.f32x2 %0, %1, %2;" : "=l"(dst) : "l"(a), "l"(b))

__device__ __forceinline__ float tanh_apx(float x) {
    float y;
    asm("tanh.approx.f32 %0, %1;" : "=f"(y) : "f"(x));
    return y;
}

// moment accumulation helper (per-thread partial for fixed k)
__device__ __forceinline__ float moment_partial(const float* __restrict__ src,
                                                int n, int k, int tid, int stride) {
    float macc = 0.f;
    for (int p = tid; p < n; p += stride) {
        float t = src[p];
        bool ok = (t > 0.f) && (t < 8.f);     // beyond 8: exp(-t^2) < e^-64
        float wp = ok ? __expf(-t * t) : 0.f;
        float base = ok ? t : 0.f;            // keep base finite -> no 0*Inf
        int kk = k;
        while (kk) { if (kk & 1) wp *= base; base *= base; kk >>= 1; }
        macc += wp;
    }
    return macc;
}

// ================= kernel 1: rollout (104 blocks x 256) =================
// Blocks 0-63: LSTM rollout for one batch each.
//   Warp w, lane l owns matvec row gate*64 + w*8 + u (gate=l>>3, u=l&7).
//   All 4 gates of a warp's 8 units live in that warp; gate activations are
//   exchanged with 3 parallel shuffles. hv is folded 8->4 with ONE shuffle and
//   stored (32 slots); the (redundant-per-warp) sigma chain sums the 32 slots
//   with packed f32x2 adds, concurrent with the matvec. One barrier per step,
//   hx/hv double-buffered on step parity.
// Blocks 64-103: expert moment k = blockIdx-64 (independent of the rollout,
//   runs on otherwise-idle SMs).
__global__ void __launch_bounds__(256, 1)
pp_rollout_kernel(const float* __restrict__ pool,
                  const float* __restrict__ Wih,
                  const float* __restrict__ Whh,
                  const float* __restrict__ bih,
                  const float* __restrict__ bhh,
                  const float* __restrict__ Vw,
                  const float* __restrict__ Vb,
                  const float* __restrict__ et) {
    const int bk   = blockIdx.x;
    const int tid  = threadIdx.x;
    const int w    = tid >> 5;
    const int l    = tid & 31;

    // ---------- expert moment blocks ----------
    if (bk >= BATCH) {
        const int k = bk - BATCH;     // 0..39
        float macc = moment_partial(et, NPTS, k, tid, 256);
        __shared__ float msum[8];
#pragma unroll
        for (int o = 16; o > 0; o >>= 1) macc += __shfl_xor_sync(0xffffffffu, macc, o);
        if (l == 0) msum[w] = macc;
        __syncthreads();
        if (tid == 0) {
            double s = (double)((msum[0] + msum[1]) + (msum[2] + msum[3]))
                     + (double)((msum[4] + msum[5]) + (msum[6] + msum[7]));
            g_Me[k] = s;
        }
        return;
    }

    // ---------- rollout blocks ----------
    const int b    = bk;
    const int gate = l >> 3;          // 0=i 1=f 2=g 3=o
    const int ug   = l & 7;           // unit within warp's group
    const int row  = gate * 64 + w * 8 + ug;

    __shared__ __align__(16) float hx_sb[2][HIDDEN];
    __shared__ __align__(16) float hv_sb[2][32];
    __shared__ __align__(16) float lg_s[SEQ_LEN];
    __shared__ __align__(16) float cum_hist[SEQ_LEN];

    // preload W_hh row as packed f32x2
    unsigned long long w2[32];
    {
        const float4* wrow = (const float4*)(Whh + row * HIDDEN);
#pragma unroll
        for (int q = 0; q < 16; q++) {
            float4 v = wrow[q];
            w2[2 * q]     = pk2(v.x, v.y);
            w2[2 * q + 1] = pk2(v.z, v.w);
        }
    }
    const float wih  = Wih[row];
    const float bias = bih[row] + bhh[row];
    const float vb   = Vb[0];
    const bool  isg  = (gate == 2);
    const float vw   = (l < 8) ? Vw[w * 8 + l] : 0.f;

    if (tid < HIDDEN) hx_sb[0][tid] = 0.f;
    if (tid < 32)     hv_sb[0][tid] = 0.f;
    if (tid < SEQ_LEN) lg_s[tid] = -__logf(pool[b * SEQ_LEN + tid]);

    float cx = 0.f;       // lanes 0..7: cell state of unit w*8+l
    float cum_v = 0.f;    // redundant in every lane of every warp
    __syncthreads();

    for (int s = 0; s < SEQ_LEN; s++) {
        const int p = s & 1;

        // ---- cum/sigma chain (redundant per warp; parallel to matvec) ----
        // sum 32 hv partials with packed f32x2 adds
        const ulonglong2* hv4 = (const ulonglong2*)hv_sb[p];
        ulonglong2 va = hv4[0], vb2 = hv4[1], vc = hv4[2], vd = hv4[3];
        unsigned long long s1, s2, s3, s4, s5, s6, s7;
        FADD2(s1, va.x, va.y);
        FADD2(s2, vb2.x, vb2.y);
        FADD2(s3, vc.x, vc.y);
        FADD2(s4, vd.x, vd.y);
        FADD2(s5, s1, s2);
        FADD2(s6, s3, s4);
        FADD2(s7, s5, s6);
        float slo, shi;
        upk2(s7, slo, shi);
        float S = slo + shi;
        float z = S + vb;
        float sigma = (z > 0.f ? z : (__expf(z) - 1.f)) + 1.f;   // elu + 1
        cum_v += __fdividef(lg_s[s], sigma);

        // ---- matvec row: m = bias + Whh[row,:] @ hx ----
        unsigned long long acc0 = pk2(bias, 0.f);
        unsigned long long acc1 = 0ull, acc2 = 0ull, acc3 = 0ull;
        const ulonglong2* h4 = (const ulonglong2*)hx_sb[p];
#pragma unroll
        for (int j = 0; j < 8; j++) {
            ulonglong2 ha = h4[2 * j];
            ulonglong2 hb = h4[2 * j + 1];
            FFMA2(acc0, w2[4 * j + 0], ha.x);
            FFMA2(acc1, w2[4 * j + 1], ha.y);
            FFMA2(acc2, w2[4 * j + 2], hb.x);
            FFMA2(acc3, w2[4 * j + 3], hb.y);
        }
        unsigned long long p0, p1, pz;
        FADD2(p0, acc0, acc1);
        FADD2(p1, acc2, acc3);
        FADD2(pz, p0, p1);
        float lo, hi;
        upk2(pz, lo, hi);
        float gv = fmaf(cum_v, wih, lo + hi);

        // ---- activation (sigmoid via tanh identity; g-gate plain tanh) ----
        float pre = isg ? gv : 0.5f * gv;
        float tv  = tanh_apx(pre);
        float act = isg ? tv : fmaf(tv, 0.5f, 0.5f);

        // ---- gather gates to unit lanes (3 parallel shuffles) ----
        float fv = __shfl_sync(0xffffffffu, act, ug + 8);
        float gg = __shfl_sync(0xffffffffu, act, ug + 16);
        float ov = __shfl_sync(0xffffffffu, act, ug + 24);

        float hv = 0.f;
        if (l < 8) {
            cx = fmaf(fv, cx, act * gg);
            float h = ov * tanh_apx(cx);
            hx_sb[p ^ 1][w * 8 + l] = h;
            hv = h * vw;
        }
        // fold 8 -> 4 with ONE shuffle; lanes 0..3 store
        hv += __shfl_xor_sync(0xffffffffu, hv, 4);
        if (l < 4) hv_sb[p ^ 1][w * 4 + l] = hv;
        if (tid == 0) cum_hist[s] = cum_v;
        __syncthreads();
    }

    // ---------------- epilogue: compaction of valid times ----------------
    if (tid < SEQ_LEN) {
        float t = cum_hist[tid];
        bool valid = (t > 0.f) && (t < T_MAX_V);
        unsigned bal = __ballot_sync(0xffffffffu, valid);
        int base = 0;
        if (l == 0) base = atomicAdd(&g_nl, __popc(bal));
        base = __shfl_sync(0xffffffffu, base, 0);
        if (valid) g_lc[base + __popc(bal & ((1u << l) - 1u))] = t;
    }
}

// ================= kernel 2: reward (256 blocks x 256) =================
// All blocks: symmetric ll pair partial -> g_llp[bk] (distinct slots, no atomics).
// Blocks 0-39: learner moment k (expert moments were done in kernel 1).
__global__ void __launch_bounds__(NTHR_B, 4)
pp_reward_kernel() {
    const int T   = NBLK_B * NTHR_B;
    const int g   = blockIdx.x * NTHR_B + threadIdx.x;
    const int bk  = blockIdx.x;
    const int tid = threadIdx.x;
    const int wrp = tid >> 5, lane = tid & 31;
    const int nl  = g_nl;

    // ---- ll pair sum (j > i, symmetric) ----
    float acc = 0.f;
    if (nl > 0) {
        const int R = T / nl;
        if (g < R * nl) {
            const int i  = g % nl;
            const int r0 = g / nl;
            const float ti = g_lc[i];
            for (int j = i + 1 + r0; j < nl; j += R) {
                float d = ti - g_lc[j];
                acc += __expf(-d * d);
            }
        }
    }
    __shared__ float bsum[8];
#pragma unroll
    for (int o = 16; o > 0; o >>= 1) acc += __shfl_xor_sync(0xffffffffu, acc, o);
    if (lane == 0) bsum[wrp] = acc;
    __syncthreads();
    if (tid == 0) {
        float s = ((bsum[0] + bsum[1]) + (bsum[2] + bsum[3]))
                + ((bsum[4] + bsum[5]) + (bsum[6] + bsum[7]));
        g_llp[bk] = s;
    }

    // ---- learner moment blocks ----
    if (bk < KTERMS) {
        float macc = moment_partial(g_lc, nl, bk, tid, NTHR_B);
        __shared__ float msum[8];
#pragma unroll
        for (int o = 16; o > 0; o >>= 1) macc += __shfl_xor_sync(0xffffffffu, macc, o);
        if (lane == 0) msum[wrp] = macc;
        __syncthreads();
        if (tid == 0) {
            double s = (double)((msum[0] + msum[1]) + (msum[2] + msum[3]))
                     + (double)((msum[4] + msum[5]) + (msum[6] + msum[7]));
            g_Ml[bk] = s;
        }
    }
}

// ================= kernel 3: finalize (1 block x 256) =================
__global__ void __launch_bounds__(NTHR_B, 1)
pp_finalize_kernel(float* __restrict__ out) {
    const int tid = threadIdx.x;
    const int wrp = tid >> 5, lane = tid & 31;

    double d = (double)g_llp[tid];
#pragma unroll
    for (int o = 16; o > 0; o >>= 1) d += __shfl_xor_sync(0xffffffffu, d, o);
    __shared__ double wsum[8];
    if (lane == 0) wsum[wrp] = d;

    __shared__ double t_ee[KTERMS], t_le[KTERMS];
    if (tid < KTERMS) {
        double c  = c_coef[tid];
        double me = g_Me[tid];
        t_ee[tid] = c * me * me;
        t_le[tid] = c * me * g_Ml[tid];
    }
    __syncthreads();

    if (tid == 0) {
        double llp = ((wsum[0] + wsum[1]) + (wsum[2] + wsum[3]))
                   + ((wsum[4] + wsum[5]) + (wsum[6] + wsum[7]));
        double e0 = 0, e1 = 0, e2 = 0, e3 = 0, l0 = 0, l1 = 0, l2 = 0, l3 = 0;
#pragma unroll
        for (int k = 0; k < KTERMS; k += 4) {
            e0 += t_ee[k]; e1 += t_ee[k + 1]; e2 += t_ee[k + 2]; e3 += t_ee[k + 3];
            l0 += t_le[k]; l1 += t_le[k + 1]; l2 += t_le[k + 2]; l3 += t_le[k + 3];
        }
        double ee = (e0 + e1) + (e2 + e3);
        double le = (l0 + l1) + (l2 + l3);
        double ll = 2.0 * llp + (double)g_nl;   // off-diag*2 + diagonal
        out[0] = (float)(ee + ll - 2.0 * le);
        g_nl = 0;                                // reset for next replay
    }
}

// ---------------- launch ----------------
extern "C" void kernel_launch(void* const* d_in, const int* in_sizes, int n_in,
                              void* d_out, int out_size) {
    const float* pool = (const float*)d_in[0];
    const float* et   = (const float*)d_in[1];
    const float* Wih  = (const float*)d_in[2];
    const float* Whh  = (const float*)d_in[3];
    const float* bih  = (const float*)d_in[4];
    const float* bhh  = (const float*)d_in[5];
    const float* Vw   = (const float*)d_in[6];
    const float* Vb   = (const float*)d_in[7];
    float* out = (float*)d_out;

    pp_rollout_kernel<<<BATCH + KTERMS, 256>>>(pool, Wih, Whh, bih, bhh, Vw, Vb, et);
    pp_reward_kernel<<<NBLK_B, NTHR_B>>>();
    pp_finalize_kernel<<<1, NTHR_B>>>(out);
}